// round 3
// baseline (speedup 1.0000x reference)
#include <cuda_runtime.h>
#include <cstdint>

#define NTOK   49
#define EMBED  128
#define NHEADS 4
#define DHEAD  32
#define NWIN   64
#define NPAIR  25          // ceil(49/2)
#define QKV_COLS 384
#define ROWP   130         // padded row stride for Q/K/V (avoids 128-float stride conflicts)

// ---- shared memory layout (floats) ----
#define XP_OFF 0
#define Q_OFF  6400
#define K_OFF  (Q_OFF + NTOK*ROWP)
#define V_OFF  (K_OFF + NTOK*ROWP)
#define S_OFF  (V_OFF + NTOK*ROWP)
#define SMEM_FLOATS (S_OFF + NTOK*50)
#define SMEM_BYTES (SMEM_FLOATS * 4)

typedef unsigned long long u64;

__device__ __forceinline__ u64 ffma2(u64 a, u64 b, u64 c) {
    u64 d;
    asm("fma.rn.f32x2 %0, %1, %2, %3;" : "=l"(d) : "l"(a), "l"(b), "l"(c));
    return d;
}
__device__ __forceinline__ u64 dup2(float x) {
    u64 d;
    unsigned int u = __float_as_uint(x);
    asm("mov.b64 %0, {%1, %1};" : "=l"(d) : "r"(u));
    return d;
}
__device__ __forceinline__ u64 pack2(float x, float y) {
    u64 d;
    unsigned int ux = __float_as_uint(x), uy = __float_as_uint(y);
    asm("mov.b64 %0, {%1, %2};" : "=l"(d) : "r"(ux), "r"(uy));
    return d;
}
__device__ __forceinline__ void unpack2(u64 v, float& x, float& y) {
    unsigned int ux, uy;
    asm("mov.b64 {%0, %1}, %2;" : "=r"(ux), "=r"(uy) : "l"(v));
    x = __uint_as_float(ux);
    y = __uint_as_float(uy);
}

__global__ __launch_bounds__(256, 2)
void win_attn_kernel(const float* __restrict__ x,
                     const float* __restrict__ qkv_w,
                     const float* __restrict__ qkv_b,
                     const float* __restrict__ proj_w,
                     const float* __restrict__ proj_b,
                     const float* __restrict__ bias_table,
                     const float* __restrict__ mask,
                     const int*   __restrict__ rel_index,
                     float*       __restrict__ out)
{
    extern __shared__ float sm[];
    float* xp = sm + XP_OFF;        // packed x (token-pairs), later reused as OS
    float* Qs = sm + Q_OFF;
    float* Ks = sm + K_OFF;
    float* Vs = sm + V_OFF;
    float* Ss = sm + S_OFF;
    float* os = sm + XP_OFF;        // attention output [n][c], stride 128

    const int tid = threadIdx.x;
    const int b   = blockIdx.x;
    const float scale = 0.17677669529663687f;   // 32^-0.5

    // ---------------- P0: load x, pack token-pairs: xp[k][tp] = (x[2tp][k], x[2tp+1][k])
    const float* xg = x + (size_t)b * NTOK * EMBED;
    for (int i = tid; i < EMBED; i += 256)
        xp[(i * NPAIR + 24) * 2 + 1] = 0.f;     // pad token 49
    for (int i = tid; i < NTOK * EMBED; i += 256) {
        int t = i >> 7, c = i & 127;
        xp[(c * NPAIR + (t >> 1)) * 2 + (t & 1)] = xg[i];
    }
    __syncthreads();

    // ---------------- P1: qkv = x @ qkv_w + b ; split into Q (scaled), K, V
    const int lane128 = tid & 127;
    const int grp     = tid >> 7;           // 0 or 1
    const int tp0     = grp ? 13 : 0;
    const int ntp     = grp ? 12 : 13;

    for (int cb = 0; cb < 3; cb++) {
        const int col = cb * 128 + lane128;       // column into qkv_w / qkv_b (0..383)
        u64 acc[13];
        #pragma unroll
        for (int t = 0; t < 13; t++) acc[t] = 0ull;

        const float* wp = qkv_w + col;
        const u64*   xb = reinterpret_cast<const u64*>(xp);
        for (int k = 0; k < EMBED; k++) {
            u64 wd = dup2(wp[(size_t)k * QKV_COLS]);
            const u64* xk = xb + k * NPAIR + tp0;
            #pragma unroll
            for (int t = 0; t < 13; t++)
                acc[t] = ffma2(xk[t], wd, acc[t]);   // grp1 t=12 is garbage, never stored
        }

        float bv   = qkv_b[col];
        float mult = (cb == 0) ? scale : 1.f;
        float* dst = (cb == 0) ? Qs : (cb == 1) ? Ks : Vs;
        #pragma unroll
        for (int t = 0; t < 13; t++) {
            if (t < ntp) {
                int tp = tp0 + t;
                float a0, a1; unpack2(acc[t], a0, a1);
                int t2 = tp * 2;
                // FIX: row-local column index is lane128 (0..127), NOT col (which
                // includes the cb*128 offset and overflowed the 130-wide rows,
                // racing into neighboring K/V rows).
                dst[t2 * ROWP + lane128] = (a0 + bv) * mult;
                if (t2 + 1 < NTOK)
                    dst[(t2 + 1) * ROWP + lane128] = (a1 + bv) * mult;
            }
        }
    }
    __syncthreads();

    // ---------------- P2: per-head attention
    const float* maskw = mask + (size_t)(b & (NWIN - 1)) * NTOK * NTOK;
    const int wid = tid >> 5, ln = tid & 31;

    for (int h = 0; h < NHEADS; h++) {
        // --- S = (Q_h K_h^T) + bias + mask
        for (int i = tid; i < NTOK * NTOK; i += 256) {
            int n = i / NTOK, m = i - n * NTOK;
            const u64* qv = reinterpret_cast<const u64*>(Qs + n * ROWP + h * DHEAD);
            const u64* kv = reinterpret_cast<const u64*>(Ks + m * ROWP + h * DHEAD);
            u64 acc = 0ull;
            #pragma unroll
            for (int j = 0; j < DHEAD / 2; j++)
                acc = ffma2(qv[j], kv[j], acc);
            float a0, a1; unpack2(acc, a0, a1);
            float sv = a0 + a1;
            sv += bias_table[rel_index[i] * NHEADS + h];
            sv += maskw[i];
            Ss[n * 50 + m] = sv;
        }
        __syncthreads();

        // --- softmax over m (warp per row)
        for (int n = wid; n < NTOK; n += 8) {
            float v0 = (ln      < NTOK) ? Ss[n * 50 + ln]      : -1e30f;
            float v1 = (ln + 32 < NTOK) ? Ss[n * 50 + ln + 32] : -1e30f;
            float mx = fmaxf(v0, v1);
            #pragma unroll
            for (int o = 16; o; o >>= 1) mx = fmaxf(mx, __shfl_xor_sync(0xffffffffu, mx, o));
            float e0 = (ln      < NTOK) ? __expf(v0 - mx) : 0.f;
            float e1 = (ln + 32 < NTOK) ? __expf(v1 - mx) : 0.f;
            float sum = e0 + e1;
            #pragma unroll
            for (int o = 16; o; o >>= 1) sum += __shfl_xor_sync(0xffffffffu, sum, o);
            float inv = 1.f / sum;
            if (ln      < NTOK) Ss[n * 50 + ln]      = e0 * inv;
            if (ln + 32 < NTOK) Ss[n * 50 + ln + 32] = e1 * inv;
        }
        __syncthreads();

        // --- O_h = S @ V_h   (channel-pair packed)
        for (int i = tid; i < NTOK * (DHEAD / 2); i += 256) {
            int n = i >> 4, dp = i & 15;
            const float* sr = Ss + n * 50;
            u64 acc = 0ull;
            for (int m = 0; m < NTOK; m++) {
                u64 vv = *reinterpret_cast<const u64*>(Vs + m * ROWP + h * DHEAD + dp * 2);
                acc = ffma2(dup2(sr[m]), vv, acc);
            }
            float a0, a1; unpack2(acc, a0, a1);
            os[n * EMBED + h * DHEAD + dp * 2]     = a0;
            os[n * EMBED + h * DHEAD + dp * 2 + 1] = a1;
        }
        __syncthreads();   // protects Ss before next head overwrites
    }

    // ---------------- P3: out = O @ proj_w + proj_b  (token-pair packed)
    {
        const int col = lane128;
        u64 acc[13];
        #pragma unroll
        for (int t = 0; t < 13; t++) acc[t] = 0ull;

        const float* wp = proj_w + col;
        for (int k = 0; k < EMBED; k++) {
            u64 wd = dup2(wp[(size_t)k * EMBED]);
            #pragma unroll
            for (int t = 0; t < 13; t++) {
                int tp = tp0 + t;
                float o0 = os[(2 * tp)     * EMBED + k];   // in-bounds smem even for pad lanes
                float o1 = os[(2 * tp + 1) * EMBED + k];
                acc[t] = ffma2(pack2(o0, o1), wd, acc[t]);
            }
        }

        float pb = proj_b[col];
        float* og = out + (size_t)b * NTOK * EMBED;
        #pragma unroll
        for (int t = 0; t < 13; t++) {
            if (t < ntp) {
                int tp = tp0 + t;
                float a0, a1; unpack2(acc[t], a0, a1);
                int t2 = tp * 2;
                og[t2 * EMBED + col] = a0 + pb;
                if (t2 + 1 < NTOK)
                    og[(t2 + 1) * EMBED + col] = a1 + pb;
            }
        }
    }
}

extern "C" void kernel_launch(void* const* d_in, const int* in_sizes, int n_in,
                              void* d_out, int out_size)
{
    // Bind inputs by element count — all eight are pairwise distinct:
    //   x:25690112  qkv_w:49152  qkv_b:384  proj_w:16384
    //   proj_b:128  bias_table:676  mask:153664  rel_index:2401
    const float* x = nullptr; const float* qkv_w = nullptr; const float* qkv_b = nullptr;
    const float* proj_w = nullptr; const float* proj_b = nullptr;
    const float* bias_table = nullptr; const float* mask = nullptr;
    const int* rel_index = nullptr;

    for (int i = 0; i < n_in; i++) {
        switch (in_sizes[i]) {
            case 25690112: x          = (const float*)d_in[i]; break;
            case 49152:    qkv_w      = (const float*)d_in[i]; break;
            case 384:      qkv_b      = (const float*)d_in[i]; break;
            case 16384:    proj_w     = (const float*)d_in[i]; break;
            case 128:      proj_b     = (const float*)d_in[i]; break;
            case 676:      bias_table = (const float*)d_in[i]; break;
            case 153664:   mask       = (const float*)d_in[i]; break;
            case 2401:     rel_index  = (const int*)  d_in[i]; break;
            default: break;
        }
    }

    float* out = (float*)d_out;

    cudaFuncSetAttribute(win_attn_kernel,
                         cudaFuncAttributeMaxDynamicSharedMemorySize, SMEM_BYTES);

    win_attn_kernel<<<4096, 256, SMEM_BYTES>>>(
        x, qkv_w, qkv_b, proj_w, proj_b, bias_table, mask, rel_index, out);
}

// round 4
// speedup vs baseline: 1.5711x; 1.5711x over previous
#include <cuda_runtime.h>
#include <cstdint>

#define NTOK   49
#define EMBED  128
#define NHEADS 4
#define DHEAD  32
#define NWIN   64
#define NPAIR  25
#define QKV_COLS 384
#define ROWP   130            // Q/K/V row stride (floats)
#define SST    52             // S row stride (floats), rows padded to 52
#define SHSZ   (SST*52)       // per-head S size = 2704

// ---- shared layout (floats) ----
// Q : 52 rows x 130            @ 0        (rows 49-51 zeroed)
// K : 52 rows x 130            @ 6760
// V : 52 rows x 130            @ 13520
// SX: XP (25*2*128=6400)  UNION  S4 (4*2704=10816)   @ 20280
// OS: packed attn out (128*25*2=6400) + 8 pad        @ 31096
#define Q_OFF  0
#define K_OFF  6760
#define V_OFF  13520
#define SX_OFF 20280
#define OS_OFF (SX_OFF + 10816)
#define SMEM_FLOATS (OS_OFF + 6400 + 8)
#define SMEM_BYTES  (SMEM_FLOATS * 4)

typedef unsigned long long u64;

__device__ __forceinline__ u64 ffma2(u64 a, u64 b, u64 c) {
    u64 d;
    asm("fma.rn.f32x2 %0, %1, %2, %3;" : "=l"(d) : "l"(a), "l"(b), "l"(c));
    return d;
}
__device__ __forceinline__ u64 dup2(float x) {
    u64 d; unsigned int u = __float_as_uint(x);
    asm("mov.b64 %0, {%1, %1};" : "=l"(d) : "r"(u));
    return d;
}
__device__ __forceinline__ void unpack2(u64 v, float& x, float& y) {
    unsigned int ux, uy;
    asm("mov.b64 {%0, %1}, %2;" : "=r"(ux), "=r"(uy) : "l"(v));
    x = __uint_as_float(ux); y = __uint_as_float(uy);
}

__global__ __launch_bounds__(512, 1)
void win_attn_kernel(const float* __restrict__ x,
                     const float* __restrict__ qkv_w,
                     const float* __restrict__ qkv_b,
                     const float* __restrict__ proj_w,
                     const float* __restrict__ proj_b,
                     const float* __restrict__ bias_table,
                     const float* __restrict__ mask,
                     const int*   __restrict__ rel_index,
                     float*       __restrict__ out)
{
    extern __shared__ float sm[];
    float* Qs = sm + Q_OFF;
    float* Ks = sm + K_OFF;
    float* Vs = sm + V_OFF;
    float* xp = sm + SX_OFF;    // token-pair-packed x (P1 input); later S4
    float* os = sm + OS_OFF;    // pair-packed attention output

    const int tid = threadIdx.x;
    const int b   = blockIdx.x;
    const float scale = 0.17677669529663687f;   // 32^-0.5

    // ================= P0: load/pack x, zero pads =================
    const float* xg = x + (size_t)b * NTOK * EMBED;
    for (int i = tid; i < 3 * ROWP; i += 512) {          // zero Q/K pad rows 49..51
        Qs[49 * ROWP + i] = 0.f;
        Ks[49 * ROWP + i] = 0.f;
    }
    if (tid < 128) xp[(tid * NPAIR + 24) * 2 + 1] = 0.f; // token-49 pad slot
    for (int i = tid; i < NTOK * EMBED; i += 512) {
        int t = i >> 7, c = i & 127;
        xp[(c * NPAIR + (t >> 1)) * 2 + (t & 1)] = xg[i];
    }
    __syncthreads();

    // ================= P1: qkv GEMM (7tp x 3cols per thread) =================
    const int c1   = tid & 127;
    const int grp  = tid >> 7;            // 0..3
    const int tp0  = grp * 7;             // 0,7,14,21
    const int ntp  = (grp == 3) ? 4 : 7;
    {
        u64 acc[3][7];
        #pragma unroll
        for (int a = 0; a < 3; a++)
            #pragma unroll
            for (int t = 0; t < 7; t++) acc[a][t] = 0ull;

        const float* wq = qkv_w + c1;
        const u64*   xb = reinterpret_cast<const u64*>(xp);
        #pragma unroll 2
        for (int k = 0; k < EMBED; k++) {
            u64 wd0 = dup2(__ldg(wq + k * QKV_COLS));
            u64 wd1 = dup2(__ldg(wq + k * QKV_COLS + 128));
            u64 wd2 = dup2(__ldg(wq + k * QKV_COLS + 256));
            const u64* xk = xb + k * NPAIR + tp0;
            #pragma unroll
            for (int t = 0; t < 7; t++) {
                u64 xv = xk[t];                 // grp3 t>=4 reads pad (in-region, unstored)
                acc[0][t] = ffma2(xv, wd0, acc[0][t]);
                acc[1][t] = ffma2(xv, wd1, acc[1][t]);
                acc[2][t] = ffma2(xv, wd2, acc[2][t]);
            }
        }
        float bq = qkv_b[c1], bk = qkv_b[128 + c1], bv = qkv_b[256 + c1];
        #pragma unroll
        for (int t = 0; t < 7; t++) {
            if (t < ntp) {
                int t2 = (tp0 + t) * 2;
                float a0, a1;
                unpack2(acc[0][t], a0, a1);
                Qs[t2 * ROWP + c1] = (a0 + bq) * scale;
                if (t2 + 1 < NTOK) Qs[(t2 + 1) * ROWP + c1] = (a1 + bq) * scale;
                unpack2(acc[1][t], a0, a1);
                Ks[t2 * ROWP + c1] = a0 + bk;
                if (t2 + 1 < NTOK) Ks[(t2 + 1) * ROWP + c1] = a1 + bk;
                unpack2(acc[2][t], a0, a1);
                Vs[t2 * ROWP + c1] = a0 + bv;
                if (t2 + 1 < NTOK) Vs[(t2 + 1) * ROWP + c1] = a1 + bv;
            }
        }
    }
    __syncthreads();

    // ================= P2a: S = QK^T + bias + mask, all 4 heads =================
    const float* maskw = mask + (size_t)(b & (NWIN - 1)) * NTOK * NTOK;
    float* S4 = sm + SX_OFF;    // xp is dead now
    for (int tile = tid; tile < 676; tile += 512) {     // 4 heads * 13nb * 13mb
        int h  = tile / 169;
        int r  = tile - h * 169;
        int nb = r / 13;
        int mb = r - nb * 13;
        const float* qr = Qs + nb * 4 * ROWP + h * DHEAD;
        const float* kr = Ks + mb * 4 * ROWP + h * DHEAD;
        u64 acc[4][4];
        #pragma unroll
        for (int i = 0; i < 4; i++)
            #pragma unroll
            for (int j = 0; j < 4; j++) acc[i][j] = 0ull;

        #pragma unroll 4
        for (int jp = 0; jp < 16; jp++) {
            u64 qv[4], kv[4];
            #pragma unroll
            for (int i = 0; i < 4; i++)
                qv[i] = *reinterpret_cast<const u64*>(qr + i * ROWP + 2 * jp);
            #pragma unroll
            for (int j = 0; j < 4; j++)
                kv[j] = *reinterpret_cast<const u64*>(kr + j * ROWP + 2 * jp);
            #pragma unroll
            for (int i = 0; i < 4; i++)
                #pragma unroll
                for (int j = 0; j < 4; j++)
                    acc[i][j] = ffma2(qv[i], kv[j], acc[i][j]);
        }
        float* Sh = S4 + h * SHSZ;
        #pragma unroll
        for (int i = 0; i < 4; i++) {
            int n = nb * 4 + i;
            #pragma unroll
            for (int j = 0; j < 4; j++) {
                int m = mb * 4 + j;
                float a0, a1; unpack2(acc[i][j], a0, a1);
                float sv = a0 + a1;
                if (n < NTOK && m < NTOK) {
                    int idx = n * NTOK + m;
                    sv += __ldg(bias_table + rel_index[idx] * NHEADS + h) + __ldg(maskw + idx);
                }
                Sh[n * SST + m] = sv;
            }
        }
    }
    __syncthreads();

    // ================= P2b: softmax (warp per row, 196 rows) =================
    {
        const int wid = tid >> 5, ln = tid & 31;
        for (int row = wid; row < NHEADS * NTOK; row += 16) {
            int h = row / NTOK, n = row - h * NTOK;
            float* Sr = S4 + h * SHSZ + n * SST;
            float v0 = (ln      < NTOK) ? Sr[ln]      : -1e30f;
            float v1 = (ln + 32 < NTOK) ? Sr[ln + 32] : -1e30f;
            float mx = fmaxf(v0, v1);
            #pragma unroll
            for (int o = 16; o; o >>= 1) mx = fmaxf(mx, __shfl_xor_sync(0xffffffffu, mx, o));
            float e0 = (ln      < NTOK) ? __expf(v0 - mx) : 0.f;
            float e1 = (ln + 32 < NTOK) ? __expf(v1 - mx) : 0.f;
            float sum = e0 + e1;
            #pragma unroll
            for (int o = 16; o; o >>= 1) sum += __shfl_xor_sync(0xffffffffu, sum, o);
            float inv = 1.f / sum;
            if (ln      < NTOK) Sr[ln]      = e0 * inv;
            if (ln + 32 < NTOK) Sr[ln + 32] = e1 * inv;
        }
    }
    __syncthreads();

    // ================= P2c: O = S @ V  (4 tok x 8 ch per thread, all heads) ====
    if (tid < 208) {                       // 13 nb * 16 chb
        int nb  = tid >> 4;                // 0..12
        int chb = tid & 15;                // 0..15  (8 channels each)
        int h   = chb >> 2;
        const float* Sh = S4 + h * SHSZ;
        const float* vb = Vs + chb * 8;
        u64 acc[4][4];
        #pragma unroll
        for (int i = 0; i < 4; i++)
            #pragma unroll
            for (int j = 0; j < 4; j++) acc[i][j] = 0ull;

        for (int m = 0; m < NTOK; m++) {
            u64 vv[4];
            #pragma unroll
            for (int j = 0; j < 4; j++)
                vv[j] = *reinterpret_cast<const u64*>(vb + m * ROWP + 2 * j);
            #pragma unroll
            for (int i = 0; i < 4; i++) {
                u64 sd = dup2(Sh[(nb * 4 + i) * SST + m]);
                #pragma unroll
                for (int j = 0; j < 4; j++)
                    acc[i][j] = ffma2(sd, vv[j], acc[i][j]);
            }
        }
        #pragma unroll
        for (int i = 0; i < 4; i++) {
            int n = nb * 4 + i;
            if (n < NTOK) {
                #pragma unroll
                for (int j = 0; j < 4; j++) {
                    int ch = chb * 8 + 2 * j;
                    float a0, a1; unpack2(acc[i][j], a0, a1);
                    os[(ch       * NPAIR + (n >> 1)) * 2 + (n & 1)] = a0;
                    os[((ch + 1) * NPAIR + (n >> 1)) * 2 + (n & 1)] = a1;
                }
            }
        }
    }
    __syncthreads();

    // ================= P3: out = O @ proj_w + proj_b =================
    {
        u64 acc[7];
        #pragma unroll
        for (int t = 0; t < 7; t++) acc[t] = 0ull;
        const u64*   ob = reinterpret_cast<const u64*>(os);
        const float* wp = proj_w + c1;
        #pragma unroll 2
        for (int k = 0; k < EMBED; k++) {
            u64 wd = dup2(__ldg(wp + k * EMBED));
            const u64* ok = ob + k * NPAIR + tp0;
            #pragma unroll
            for (int t = 0; t < 7; t++)
                acc[t] = ffma2(ok[t], wd, acc[t]);
        }
        float pb = proj_b[c1];
        float* og = out + (size_t)b * NTOK * EMBED;
        #pragma unroll
        for (int t = 0; t < 7; t++) {
            if (t < ntp) {
                int t2 = (tp0 + t) * 2;
                float a0, a1; unpack2(acc[t], a0, a1);
                og[t2 * EMBED + c1] = a0 + pb;
                if (t2 + 1 < NTOK) og[(t2 + 1) * EMBED + c1] = a1 + pb;
            }
        }
    }
}

extern "C" void kernel_launch(void* const* d_in, const int* in_sizes, int n_in,
                              void* d_out, int out_size)
{
    // Bind by element count (all pairwise distinct).
    const float* x = nullptr; const float* qkv_w = nullptr; const float* qkv_b = nullptr;
    const float* proj_w = nullptr; const float* proj_b = nullptr;
    const float* bias_table = nullptr; const float* mask = nullptr;
    const int* rel_index = nullptr;

    for (int i = 0; i < n_in; i++) {
        switch (in_sizes[i]) {
            case 25690112: x          = (const float*)d_in[i]; break;
            case 49152:    qkv_w      = (const float*)d_in[i]; break;
            case 384:      qkv_b      = (const float*)d_in[i]; break;
            case 16384:    proj_w     = (const float*)d_in[i]; break;
            case 128:      proj_b     = (const float*)d_in[i]; break;
            case 676:      bias_table = (const float*)d_in[i]; break;
            case 153664:   mask       = (const float*)d_in[i]; break;
            case 2401:     rel_index  = (const int*)  d_in[i]; break;
            default: break;
        }
    }

    float* out = (float*)d_out;

    cudaFuncSetAttribute(win_attn_kernel,
                         cudaFuncAttributeMaxDynamicSharedMemorySize, SMEM_BYTES);

    win_attn_kernel<<<4096, 512, SMEM_BYTES>>>(
        x, qkv_w, qkv_b, proj_w, proj_b, bias_table, mask, rel_index, out);
}

// round 5
// speedup vs baseline: 2.3769x; 1.5129x over previous
#include <cuda_runtime.h>
#include <cstdint>

#define NTOK   49
#define EMBED  128
#define NHEADS 4
#define DHEAD  32
#define NWIN   64
#define NPAIR  25
#define QKV_COLS 384
#define ROWP   130            // Q/K/V row stride (floats), 49 rows each
#define SST    49             // S row stride
#define SHS    (SST*NTOK)     // per-head S = 2401

// ---- shared layout (floats), total 28714 fl = 114,856 B ----
// Q  : 49x130 @ 0        (dead after P2a; OS overlays here)
// K  : 49x130 @ 6370     (dead after P2a)
// V  : 49x130 @ 12740
// SX : xp (6400) UNION S4 (4x2401 = 9604) @ 19110
// OS : 6400 fl @ 0 (over Q / start of K)
#define Q_OFF  0
#define K_OFF  6370
#define V_OFF  12740
#define SX_OFF 19110
#define SMEM_FLOATS (SX_OFF + 9604)
#define SMEM_BYTES  (SMEM_FLOATS * 4)

typedef unsigned long long u64;

__device__ __forceinline__ u64 ffma2(u64 a, u64 b, u64 c) {
    u64 d;
    asm("fma.rn.f32x2 %0, %1, %2, %3;" : "=l"(d) : "l"(a), "l"(b), "l"(c));
    return d;
}
__device__ __forceinline__ u64 dup2(float x) {
    u64 d; unsigned int u = __float_as_uint(x);
    asm("mov.b64 %0, {%1, %1};" : "=l"(d) : "r"(u));
    return d;
}
__device__ __forceinline__ void unpack2(u64 v, float& x, float& y) {
    unsigned int ux, uy;
    asm("mov.b64 {%0, %1}, %2;" : "=r"(ux), "=r"(uy) : "l"(v));
    x = __uint_as_float(ux); y = __uint_as_float(uy);
}
__device__ __forceinline__ int imin(int a, int b) { return a < b ? a : b; }

__global__ __launch_bounds__(256, 2)
void win_attn_kernel(const float* __restrict__ x,
                     const float* __restrict__ qkv_w,
                     const float* __restrict__ qkv_b,
                     const float* __restrict__ proj_w,
                     const float* __restrict__ proj_b,
                     const float* __restrict__ bias_table,
                     const float* __restrict__ mask,
                     const int*   __restrict__ rel_index,
                     float*       __restrict__ out)
{
    extern __shared__ float sm[];
    float* Qs = sm + Q_OFF;
    float* Ks = sm + K_OFF;
    float* Vs = sm + V_OFF;
    float* xp = sm + SX_OFF;     // packed x during P1; S4 afterwards
    float* S4 = sm + SX_OFF;
    float* os = sm + Q_OFF;      // pair-packed attn output (Q/K dead by then)

    const int tid = threadIdx.x;
    const int b   = blockIdx.x;
    const float scale = 0.17677669529663687f;   // 32^-0.5

    // ================= P0: load/pack x =================
    const float* xg = x + (size_t)b * NTOK * EMBED;
    if (tid < 128) xp[(tid * NPAIR + 24) * 2 + 1] = 0.f;   // token-49 pad
    for (int i = tid; i < NTOK * EMBED; i += 256) {
        int t = i >> 7, c = i & 127;
        xp[(c * NPAIR + (t >> 1)) * 2 + (t & 1)] = xg[i];
    }
    __syncthreads();

    // ================= P1: qkv GEMM — 13 token-pairs x 3 cols per thread ======
    const int c1  = tid & 127;
    const int grp = tid >> 7;                 // 0 or 1
    const int tp0 = grp * 13;                 // 0 or 13
    const int ntp = grp ? 12 : 13;
    {
        u64 acc0[13], acc1[13], acc2[13];
        #pragma unroll
        for (int t = 0; t < 13; t++) { acc0[t] = 0ull; acc1[t] = 0ull; acc2[t] = 0ull; }

        const float* wq = qkv_w + c1;
        const u64*   xb = reinterpret_cast<const u64*>(xp);
        float w0 = __ldg(wq), w1 = __ldg(wq + 128), w2 = __ldg(wq + 256);
        #pragma unroll 2
        for (int k = 0; k < EMBED; k++) {
            u64 d0 = dup2(w0), d1 = dup2(w1), d2 = dup2(w2);
            if (k < EMBED - 1) {              // software-pipelined weight prefetch
                const float* wn = wq + (k + 1) * QKV_COLS;
                w0 = __ldg(wn); w1 = __ldg(wn + 128); w2 = __ldg(wn + 256);
            }
            const u64* xk = xb + k * NPAIR + tp0;
            #pragma unroll
            for (int t = 0; t < 13; t++) {
                u64 xv = xk[t];               // grp1 t=12 reads in-region garbage, never stored
                acc0[t] = ffma2(xv, d0, acc0[t]);
                acc1[t] = ffma2(xv, d1, acc1[t]);
                acc2[t] = ffma2(xv, d2, acc2[t]);
            }
        }
        float bq = qkv_b[c1], bk = qkv_b[128 + c1], bv = qkv_b[256 + c1];
        #pragma unroll
        for (int t = 0; t < 13; t++) {
            if (t < ntp) {
                int t2 = (tp0 + t) * 2;
                float a0, a1;
                unpack2(acc0[t], a0, a1);
                Qs[t2 * ROWP + c1] = (a0 + bq) * scale;
                if (t2 + 1 < NTOK) Qs[(t2 + 1) * ROWP + c1] = (a1 + bq) * scale;
                unpack2(acc1[t], a0, a1);
                Ks[t2 * ROWP + c1] = a0 + bk;
                if (t2 + 1 < NTOK) Ks[(t2 + 1) * ROWP + c1] = a1 + bk;
                unpack2(acc2[t], a0, a1);
                Vs[t2 * ROWP + c1] = a0 + bv;
                if (t2 + 1 < NTOK) Vs[(t2 + 1) * ROWP + c1] = a1 + bv;
            }
        }
    }
    __syncthreads();

    // ================= P2a: S = QK^T + bias + mask (all 4 heads) =============
    const float* maskw = mask + (size_t)(b & (NWIN - 1)) * NTOK * NTOK;
    for (int tile = tid; tile < 676; tile += 256) {   // 4h * 13nb * 13mb
        int h  = tile / 169;
        int r  = tile - h * 169;
        int nb = r / 13;
        int mb = r - nb * 13;
        const float* qp[4];
        const float* kp[4];
        #pragma unroll
        for (int i = 0; i < 4; i++) {
            qp[i] = Qs + imin(nb * 4 + i, 48) * ROWP + h * DHEAD;   // clamp: pad rows
            kp[i] = Ks + imin(mb * 4 + i, 48) * ROWP + h * DHEAD;
        }
        u64 acc[4][4];
        #pragma unroll
        for (int i = 0; i < 4; i++)
            #pragma unroll
            for (int j = 0; j < 4; j++) acc[i][j] = 0ull;

        #pragma unroll 4
        for (int jp = 0; jp < 16; jp++) {
            u64 qv[4], kv[4];
            #pragma unroll
            for (int i = 0; i < 4; i++) qv[i] = *reinterpret_cast<const u64*>(qp[i] + 2 * jp);
            #pragma unroll
            for (int j = 0; j < 4; j++) kv[j] = *reinterpret_cast<const u64*>(kp[j] + 2 * jp);
            #pragma unroll
            for (int i = 0; i < 4; i++)
                #pragma unroll
                for (int j = 0; j < 4; j++)
                    acc[i][j] = ffma2(qv[i], kv[j], acc[i][j]);
        }
        float* Sh = S4 + h * SHS;
        #pragma unroll
        for (int i = 0; i < 4; i++) {
            int n = nb * 4 + i;
            #pragma unroll
            for (int j = 0; j < 4; j++) {
                int m = mb * 4 + j;
                if (n < NTOK && m < NTOK) {
                    float a0, a1; unpack2(acc[i][j], a0, a1);
                    int idx = n * NTOK + m;
                    Sh[n * SST + m] = a0 + a1
                        + __ldg(bias_table + rel_index[idx] * NHEADS + h)
                        + __ldg(maskw + idx);
                }
            }
        }
    }
    __syncthreads();

    // ================= P2b: softmax (warp per row, 196 rows) =================
    {
        const int wid = tid >> 5, ln = tid & 31;
        for (int row = wid; row < NHEADS * NTOK; row += 8) {
            int h = row / NTOK, n = row - h * NTOK;
            float* Sr = S4 + h * SHS + n * SST;
            float v0 = Sr[ln];
            float v1 = (ln + 32 < NTOK) ? Sr[ln + 32] : -1e30f;
            float mx = fmaxf(v0, v1);
            #pragma unroll
            for (int o = 16; o; o >>= 1) mx = fmaxf(mx, __shfl_xor_sync(0xffffffffu, mx, o));
            float e0 = (ln      < NTOK) ? __expf(v0 - mx) : 0.f;
            float e1 = (ln + 32 < NTOK) ? __expf(v1 - mx) : 0.f;
            float sum = e0 + e1;
            #pragma unroll
            for (int o = 16; o; o >>= 1) sum += __shfl_xor_sync(0xffffffffu, sum, o);
            float inv = 1.f / sum;
            if (ln      < NTOK) Sr[ln]      = e0 * inv;
            if (ln + 32 < NTOK) Sr[ln + 32] = e1 * inv;
        }
    }
    __syncthreads();

    // ================= P2c: O = S @ V (4 tok x 8 ch per thread) ==============
    if (tid < 208) {                       // 13 nb * 16 chb
        int nb  = tid >> 4;                // 0..12
        int chb = tid & 15;                // 8 channels each
        int h   = chb >> 2;
        const float* vb = Vs + chb * 8;
        const float* Srow[4];
        #pragma unroll
        for (int i = 0; i < 4; i++)
            Srow[i] = S4 + h * SHS + imin(nb * 4 + i, 48) * SST;   // clamp pad rows
        u64 acc[4][4];
        #pragma unroll
        for (int i = 0; i < 4; i++)
            #pragma unroll
            for (int j = 0; j < 4; j++) acc[i][j] = 0ull;

        #pragma unroll 2
        for (int m = 0; m < NTOK; m++) {
            u64 vv[4];
            #pragma unroll
            for (int j = 0; j < 4; j++)
                vv[j] = *reinterpret_cast<const u64*>(vb + m * ROWP + 2 * j);
            #pragma unroll
            for (int i = 0; i < 4; i++) {
                u64 sd = dup2(Srow[i][m]);
                #pragma unroll
                for (int j = 0; j < 4; j++)
                    acc[i][j] = ffma2(sd, vv[j], acc[i][j]);
            }
        }
        #pragma unroll
        for (int i = 0; i < 4; i++) {
            int n = nb * 4 + i;
            if (n < NTOK) {
                #pragma unroll
                for (int j = 0; j < 4; j++) {
                    int ch = chb * 8 + 2 * j;
                    float a0, a1; unpack2(acc[i][j], a0, a1);
                    os[(ch       * NPAIR + (n >> 1)) * 2 + (n & 1)] = a0;
                    os[((ch + 1) * NPAIR + (n >> 1)) * 2 + (n & 1)] = a1;
                }
            }
        }
    }
    __syncthreads();

    // ================= P3: out = O @ proj_w + proj_b =================
    {
        u64 acc[13];
        #pragma unroll
        for (int t = 0; t < 13; t++) acc[t] = 0ull;
        const u64*   ob = reinterpret_cast<const u64*>(os);
        const float* wp = proj_w + c1;
        float w0 = __ldg(wp);
        #pragma unroll 2
        for (int k = 0; k < EMBED; k++) {
            u64 wd = dup2(w0);
            if (k < EMBED - 1) w0 = __ldg(wp + (k + 1) * EMBED);
            const u64* ok = ob + k * NPAIR + tp0;
            #pragma unroll
            for (int t = 0; t < 13; t++)
                acc[t] = ffma2(ok[t], wd, acc[t]);
        }
        float pb = proj_b[c1];
        float* og = out + (size_t)b * NTOK * EMBED;
        #pragma unroll
        for (int t = 0; t < 13; t++) {
            if (t < ntp) {
                int t2 = (tp0 + t) * 2;
                float a0, a1; unpack2(acc[t], a0, a1);
                og[t2 * EMBED + c1] = a0 + pb;
                if (t2 + 1 < NTOK) og[(t2 + 1) * EMBED + c1] = a1 + pb;
            }
        }
    }
}

extern "C" void kernel_launch(void* const* d_in, const int* in_sizes, int n_in,
                              void* d_out, int out_size)
{
    // Bind by element count (all pairwise distinct).
    const float* x = nullptr; const float* qkv_w = nullptr; const float* qkv_b = nullptr;
    const float* proj_w = nullptr; const float* proj_b = nullptr;
    const float* bias_table = nullptr; const float* mask = nullptr;
    const int* rel_index = nullptr;

    for (int i = 0; i < n_in; i++) {
        switch (in_sizes[i]) {
            case 25690112: x          = (const float*)d_in[i]; break;
            case 49152:    qkv_w      = (const float*)d_in[i]; break;
            case 384:      qkv_b      = (const float*)d_in[i]; break;
            case 16384:    proj_w     = (const float*)d_in[i]; break;
            case 128:      proj_b     = (const float*)d_in[i]; break;
            case 676:      bias_table = (const float*)d_in[i]; break;
            case 153664:   mask       = (const float*)d_in[i]; break;
            case 2401:     rel_index  = (const int*)  d_in[i]; break;
            default: break;
        }
    }

    float* out = (float*)d_out;

    cudaFuncSetAttribute(win_attn_kernel,
                         cudaFuncAttributeMaxDynamicSharedMemorySize, SMEM_BYTES);

    win_attn_kernel<<<4096, 256, SMEM_BYTES>>>(
        x, qkv_w, qkv_b, proj_w, proj_b, bias_table, mask, rel_index, out);
}